// round 4
// baseline (speedup 1.0000x reference)
#include <cuda_runtime.h>
#include <cuda_bf16.h>
#include <math.h>
#include <stdint.h>

#define NN 20000
#define NNPAD 20096          // 157 * 128
#define EE 640000
#define HH 4
#define FDIM 256
#define MAXE 512

// ---------------- scratch ----------------------------------------------------
__device__ float g_xh[NN * FDIM];
__device__ float g_as[NN * HH];
__device__ float g_ad[NN * HH];
__device__ float g_aek[HH];
__device__ int   g_deg[NN];
__device__ int   g_rowptr[NN + 1];
__device__ int   g_cursor[NN];
__device__ int   g_eid[EE];
__device__ __nv_bfloat16 g_A3[(size_t)NNPAD * 768];
__device__ __nv_bfloat16 g_B3[768 * 256];

// ---------------- helpers ----------------------------------------------------
__device__ __forceinline__ uint32_t smem_u32(const void* p) {
    uint32_t a;
    asm("{ .reg .u64 t; cvta.to.shared.u64 t, %1; cvt.u32.u64 %0, t; }" : "=r"(a) : "l"(p));
    return a;
}
__device__ __forceinline__ void ldsm_x4(uint32_t addr, uint32_t& r0, uint32_t& r1,
                                        uint32_t& r2, uint32_t& r3) {
    asm volatile("ldmatrix.sync.aligned.m8n8.x4.shared.b16 {%0,%1,%2,%3}, [%4];"
                 : "=r"(r0), "=r"(r1), "=r"(r2), "=r"(r3) : "r"(addr));
}
__device__ __forceinline__ void ldsm_x4t(uint32_t addr, uint32_t& r0, uint32_t& r1,
                                         uint32_t& r2, uint32_t& r3) {
    asm volatile("ldmatrix.sync.aligned.m8n8.x4.trans.shared.b16 {%0,%1,%2,%3}, [%4];"
                 : "=r"(r0), "=r"(r1), "=r"(r2), "=r"(r3) : "r"(addr));
}
__device__ __forceinline__ void mma16816(float* d, const uint32_t* a, uint32_t b0, uint32_t b1) {
    asm volatile(
        "mma.sync.aligned.m16n8k16.row.col.f32.bf16.bf16.f32 "
        "{%0,%1,%2,%3}, {%4,%5,%6,%7}, {%8,%9}, {%0,%1,%2,%3};"
        : "+f"(d[0]), "+f"(d[1]), "+f"(d[2]), "+f"(d[3])
        : "r"(a[0]), "r"(a[1]), "r"(a[2]), "r"(a[3]), "r"(b0), "r"(b1));
}
__device__ __forceinline__ float lrelu(float x) { return x > 0.f ? x : 0.2f * x; }

// ---------------- CSR build -------------------------------------------------
__global__ void k_zero()
{
    int i = blockIdx.x * blockDim.x + threadIdx.x;
    if (i < NN) { g_deg[i] = 0; g_cursor[i] = 0; }
}

__global__ void k_deg(const int* __restrict__ dst)
{
    int i0 = (blockIdx.x * blockDim.x + threadIdx.x) * 4;
#pragma unroll
    for (int j = 0; j < 4; j++) {
        int i = i0 + j;
        if (i < EE) atomicAdd(&g_deg[dst[i]], 1);
    }
}

__global__ void k_scan()
{
    __shared__ int s[1024];
    int t = threadIdx.x;
    const int CH = (NN + 1023) / 1024;
    int base = t * CH;
    int sum = 0;
    for (int i = 0; i < CH; i++) {
        int idx = base + i;
        if (idx < NN) sum += g_deg[idx];
    }
    s[t] = sum;
    __syncthreads();
    for (int off = 1; off < 1024; off <<= 1) {
        int v = (t >= off) ? s[t - off] : 0;
        __syncthreads();
        s[t] += v;
        __syncthreads();
    }
    int run = s[t] - sum;
    for (int i = 0; i < CH; i++) {
        int idx = base + i;
        if (idx < NN) { g_rowptr[idx] = run; run += g_deg[idx]; }
    }
    if (t == 1023) g_rowptr[NN] = s[1023];
}

__global__ void k_fill(const int* __restrict__ dst)
{
    int i0 = (blockIdx.x * blockDim.x + threadIdx.x) * 4;
#pragma unroll
    for (int j = 0; j < 4; j++) {
        int e = i0 + j;
        if (e < EE) {
            int d = dst[e];
            int pos = atomicAdd(&g_cursor[d], 1);
            g_eid[g_rowptr[d] + pos] = e;
        }
    }
}

// ---------------- bf16-split conversions ------------------------------------
__global__ void k_cvtA(const float* __restrict__ src, int K, int total)
{
    int i = blockIdx.x * blockDim.x + threadIdx.x;
    if (i >= total) return;
    int m = i / K, k = i - m * K;
    float v = src[i];
    __nv_bfloat16 h = __float2bfloat16_rn(v);
    __nv_bfloat16 l = __float2bfloat16_rn(v - __bfloat162float(h));
    size_t base = (size_t)m * (3 * K);
    g_A3[base + k] = h;
    g_A3[base + K + k] = h;
    g_A3[base + 2 * K + k] = l;
}

__global__ void k_cvtW(const float* __restrict__ W, int K)
{
    int i = blockIdx.x * blockDim.x + threadIdx.x;
    if (i >= K * 256) return;
    int k = i >> 8, n = i & 255;
    float v = W[i];
    __nv_bfloat16 h = __float2bfloat16_rn(v);
    __nv_bfloat16 l = __float2bfloat16_rn(v - __bfloat162float(h));
    g_B3[(size_t)k * 256 + n] = h;
    g_B3[(size_t)(K + k) * 256 + n] = l;
    g_B3[(size_t)(2 * K + k) * 256 + n] = h;
}

// ---------------- HMMA GEMM: C[M,256] = A'[M,K'] @ B'[K',256] ---------------
#define ASTR 40
#define BSTR 136

__device__ __forceinline__ void gemm_load(uint32_t as_dst, uint32_t bs_dst,
                                          const __nv_bfloat16* __restrict__ A,
                                          const __nv_bfloat16* __restrict__ B,
                                          int row0, int n0, int k0, int Kp, int tid)
{
#pragma unroll
    for (int c = tid; c < 512; c += 256) {
        int r = c >> 2, off = c & 3;
        uint32_t d = as_dst + (uint32_t)(r * ASTR + off * 8) * 2;
        const void* s = A + (size_t)(row0 + r) * Kp + k0 + off * 8;
        asm volatile("cp.async.cg.shared.global [%0], [%1], 16;" :: "r"(d), "l"(s));
    }
#pragma unroll
    for (int c = tid; c < 512; c += 256) {
        int r = c >> 4, off = c & 15;
        uint32_t d = bs_dst + (uint32_t)(r * BSTR + off * 8) * 2;
        const void* s = B + (size_t)(k0 + r) * 256 + n0 + off * 8;
        asm volatile("cp.async.cg.shared.global [%0], [%1], 16;" :: "r"(d), "l"(s));
    }
    asm volatile("cp.async.commit_group;");
}

__global__ void __launch_bounds__(256, 2)
k_gemm_mma(const __nv_bfloat16* __restrict__ A, const __nv_bfloat16* __restrict__ B,
           float* __restrict__ C, int Kp)
{
    __shared__ __align__(16) __nv_bfloat16 As[2][128 * ASTR];
    __shared__ __align__(16) __nv_bfloat16 Bs[2][32 * BSTR];
    int tid = threadIdx.x;
    int wid = tid >> 5, lane = tid & 31;
    int row0 = blockIdx.y * 128;
    int n0 = blockIdx.x * 128;
    int wm = (wid >> 2) * 64;
    int wn = (wid & 3) * 32;

    float acc[4][4][4];
#pragma unroll
    for (int i = 0; i < 4; i++)
#pragma unroll
        for (int j = 0; j < 4; j++)
#pragma unroll
            for (int q = 0; q < 4; q++) acc[i][j][q] = 0.f;

    uint32_t asb = smem_u32(As), bsb = smem_u32(Bs);
    const int NIT = Kp >> 5;

    gemm_load(asb, bsb, A, B, row0, n0, 0, Kp, tid);

    for (int it = 0; it < NIT; it++) {
        int buf = it & 1;
        if (it + 1 < NIT) {
            gemm_load(asb + ((it + 1) & 1) * 128 * ASTR * 2,
                      bsb + ((it + 1) & 1) * 32 * BSTR * 2,
                      A, B, row0, n0, (it + 1) * 32, Kp, tid);
            asm volatile("cp.async.wait_group 1;");
        } else {
            asm volatile("cp.async.wait_group 0;");
        }
        __syncthreads();

        uint32_t abuf = asb + buf * 128 * ASTR * 2;
        uint32_t bbuf = bsb + buf * 32 * BSTR * 2;
#pragma unroll
        for (int ks = 0; ks < 32; ks += 16) {
            uint32_t af[4][4];
            int arow = wm + (lane & 7) + ((lane & 8) ? 8 : 0);
            int acol = ks + ((lane & 16) ? 8 : 0);
#pragma unroll
            for (int ms = 0; ms < 4; ms++) {
                uint32_t ad = abuf + (uint32_t)((arow + ms * 16) * ASTR + acol) * 2;
                ldsm_x4(ad, af[ms][0], af[ms][1], af[ms][2], af[ms][3]);
            }
            uint32_t bfr[2][4];
            int bk = ks + ((lane & 8) ? 8 : 0) + (lane & 7);
            int bnl = ((lane & 16) ? 8 : 0);
#pragma unroll
            for (int p = 0; p < 2; p++) {
                uint32_t bd = bbuf + (uint32_t)(bk * BSTR + wn + p * 16 + bnl) * 2;
                ldsm_x4t(bd, bfr[p][0], bfr[p][1], bfr[p][2], bfr[p][3]);
            }
#pragma unroll
            for (int ms = 0; ms < 4; ms++)
#pragma unroll
                for (int ns = 0; ns < 4; ns++) {
                    int p = ns >> 1, q = ns & 1;
                    mma16816(acc[ms][ns], af[ms], bfr[p][q * 2], bfr[p][q * 2 + 1]);
                }
        }
        __syncthreads();
    }

#pragma unroll
    for (int ms = 0; ms < 4; ms++) {
        int r0 = row0 + wm + ms * 16 + (lane >> 2);
#pragma unroll
        for (int ns = 0; ns < 4; ns++) {
            int cc = n0 + wn + ns * 8 + (lane & 3) * 2;
            if (r0 < NN) {
                C[(size_t)r0 * 256 + cc]     = acc[ms][ns][0];
                C[(size_t)r0 * 256 + cc + 1] = acc[ms][ns][1];
            }
            if (r0 + 8 < NN) {
                C[(size_t)(r0 + 8) * 256 + cc]     = acc[ms][ns][2];
                C[(size_t)(r0 + 8) * 256 + cc + 1] = acc[ms][ns][3];
            }
        }
    }
}

// ---------------- alpha_src / alpha_dst per node (+aek in block 0) ----------
__global__ void k_asad(const float* __restrict__ xh,
                       const float* __restrict__ a_src,
                       const float* __restrict__ a_dst,
                       const float* __restrict__ We,
                       const float* __restrict__ ae)
{
    int n = blockIdx.x;
    int t = threadIdx.x;  // 256
    float v = xh[(size_t)n * FDIM + t];
    float ps = v * a_src[t];
    float pd = v * a_dst[t];
#pragma unroll
    for (int off = 16; off > 0; off >>= 1) {
        ps += __shfl_down_sync(0xffffffffu, ps, off);
        pd += __shfl_down_sync(0xffffffffu, pd, off);
    }
    __shared__ float ss[8], sd[8];
    int w = t >> 5, lane = t & 31;
    if (lane == 0) { ss[w] = ps; sd[w] = pd; }
    __syncthreads();
    if (t < HH) {
        g_as[n * HH + t] = ss[2 * t] + ss[2 * t + 1];
        g_ad[n * HH + t] = sd[2 * t] + sd[2 * t + 1];
    }
    if (n == 0) {
        __syncthreads();
        float p = We[t] * ae[t];
#pragma unroll
        for (int off = 16; off > 0; off >>= 1)
            p += __shfl_down_sync(0xffffffffu, p, off);
        if (lane == 0) ss[w] = p;
        __syncthreads();
        if (t < HH) g_aek[t] = ss[2 * t] + ss[2 * t + 1];
    }
}

// ---------------- fused edge kernel: alpha + softmax + norm + aggregate -----
// mode 1: write bf16 triple (layer1 -> A3 for layer-2 GEMM, bias folded)
// mode 0: write fp32 out (final h)
__global__ void __launch_bounds__(256)
k_edge(const int* __restrict__ src, const float* __restrict__ eattr,
       const float* __restrict__ eatten, const float* __restrict__ xh,
       const float* __restrict__ bias, float* __restrict__ w_out,
       float* __restrict__ out_f32, int mode)
{
    __shared__ int   s_src[MAXE];
    __shared__ int   s_e[MAXE];
    __shared__ float s_att[MAXE];
    __shared__ float s_co[MAXE * 4];
    __shared__ float s_red[32];
    __shared__ float s_bcm[4], s_bcd[4];
    __shared__ float s_row[256];

    int n = blockIdx.x;
    int t = threadIdx.x;
    int lane = t & 31, warp = t >> 5, h = t >> 6;
    int lo = g_rowptr[n], hi = g_rowptr[n + 1];
    int deg = hi - lo;
    float4 ad4 = *(const float4*)&g_ad[n * 4];
    float4 ak = *(const float4*)g_aek;

    float val;
    if (deg <= MAXE) {
        // stage edges + compute alpha + local max
        float4 m = make_float4(-INFINITY, -INFINITY, -INFINITY, -INFINITY);
        for (int i = t; i < deg; i += 256) {
            int e = g_eid[lo + i];
            int s = src[e];
            float4 as4 = *(const float4*)&g_as[s * 4];
            float ea = eattr[e];
            float4 a;
            a.x = lrelu(as4.x + ad4.x + ak.x * ea);
            a.y = lrelu(as4.y + ad4.y + ak.y * ea);
            a.z = lrelu(as4.z + ad4.z + ak.z * ea);
            a.w = lrelu(as4.w + ad4.w + ak.w * ea);
            s_src[i] = s; s_e[i] = e; s_att[i] = eatten[e];
            ((float4*)s_co)[i] = a;
            m.x = fmaxf(m.x, a.x); m.y = fmaxf(m.y, a.y);
            m.z = fmaxf(m.z, a.z); m.w = fmaxf(m.w, a.w);
        }
        // block max reduce
#pragma unroll
        for (int off = 16; off > 0; off >>= 1) {
            m.x = fmaxf(m.x, __shfl_xor_sync(0xffffffffu, m.x, off));
            m.y = fmaxf(m.y, __shfl_xor_sync(0xffffffffu, m.y, off));
            m.z = fmaxf(m.z, __shfl_xor_sync(0xffffffffu, m.z, off));
            m.w = fmaxf(m.w, __shfl_xor_sync(0xffffffffu, m.w, off));
        }
        if (lane == 0) { s_red[warp * 4] = m.x; s_red[warp * 4 + 1] = m.y;
                         s_red[warp * 4 + 2] = m.z; s_red[warp * 4 + 3] = m.w; }
        __syncthreads();
        if (t == 0) {
            float4 r = make_float4(s_red[0], s_red[1], s_red[2], s_red[3]);
            for (int w2 = 1; w2 < 8; w2++) {
                r.x = fmaxf(r.x, s_red[w2 * 4]); r.y = fmaxf(r.y, s_red[w2 * 4 + 1]);
                r.z = fmaxf(r.z, s_red[w2 * 4 + 2]); r.w = fmaxf(r.w, s_red[w2 * 4 + 3]);
            }
            s_bcm[0] = r.x; s_bcm[1] = r.y; s_bcm[2] = r.z; s_bcm[3] = r.w;
        }
        __syncthreads();
        float4 m4 = make_float4(s_bcm[0], s_bcm[1], s_bcm[2], s_bcm[3]);
        // sum exp
        float4 sm = make_float4(0.f, 0.f, 0.f, 0.f);
        for (int i = t; i < deg; i += 256) {
            float4 a = ((float4*)s_co)[i];
            sm.x += expf(a.x - m4.x); sm.y += expf(a.y - m4.y);
            sm.z += expf(a.z - m4.z); sm.w += expf(a.w - m4.w);
        }
#pragma unroll
        for (int off = 16; off > 0; off >>= 1) {
            sm.x += __shfl_xor_sync(0xffffffffu, sm.x, off);
            sm.y += __shfl_xor_sync(0xffffffffu, sm.y, off);
            sm.z += __shfl_xor_sync(0xffffffffu, sm.z, off);
            sm.w += __shfl_xor_sync(0xffffffffu, sm.w, off);
        }
        if (lane == 0) { s_red[warp * 4] = sm.x; s_red[warp * 4 + 1] = sm.y;
                         s_red[warp * 4 + 2] = sm.z; s_red[warp * 4 + 3] = sm.w; }
        __syncthreads();
        if (t == 0) {
            float4 r = make_float4(0.f, 0.f, 0.f, 0.f);
            for (int w2 = 0; w2 < 8; w2++) {
                r.x += s_red[w2 * 4]; r.y += s_red[w2 * 4 + 1];
                r.z += s_red[w2 * 4 + 2]; r.w += s_red[w2 * 4 + 3];
            }
            s_bcd[0] = 1.f / (r.x + 1e-16f); s_bcd[1] = 1.f / (r.y + 1e-16f);
            s_bcd[2] = 1.f / (r.z + 1e-16f); s_bcd[3] = 1.f / (r.w + 1e-16f);
        }
        __syncthreads();
        float4 rd = make_float4(s_bcd[0], s_bcd[1], s_bcd[2], s_bcd[3]);
        // coeff + w_out
        for (int i = t; i < deg; i += 256) {
            float4 a = ((float4*)s_co)[i];
            float4 w;
            w.x = expf(a.x - m4.x) * rd.x; w.y = expf(a.y - m4.y) * rd.y;
            w.z = expf(a.z - m4.z) * rd.z; w.w = expf(a.w - m4.w) * rd.w;
            *(float4*)&w_out[(size_t)s_e[i] * 4] = w;
            float at = s_att[i];
            float4 c = make_float4(w.x * at, w.y * at, w.z * at, w.w * at);
            ((float4*)s_co)[i] = c;
        }
        __syncthreads();
        // aggregation
        float acc0 = 0.f, acc1 = 0.f;
        int i = 0;
#pragma unroll 2
        for (; i + 1 < deg; i += 2) {
            acc0 += xh[(size_t)s_src[i] * 256 + t] * s_co[i * 4 + h];
            acc1 += xh[(size_t)s_src[i + 1] * 256 + t] * s_co[(i + 1) * 4 + h];
        }
        if (i < deg) acc0 += xh[(size_t)s_src[i] * 256 + t] * s_co[i * 4 + h];
        val = acc0 + acc1 + bias[t];
    } else {
        // rare fallback: deg > MAXE, recompute alpha per pass
        float4 m = make_float4(-INFINITY, -INFINITY, -INFINITY, -INFINITY);
        for (int i = t; i < deg; i += 256) {
            int e = g_eid[lo + i];
            int s = src[e];
            float4 as4 = *(const float4*)&g_as[s * 4];
            float ea = eattr[e];
            m.x = fmaxf(m.x, lrelu(as4.x + ad4.x + ak.x * ea));
            m.y = fmaxf(m.y, lrelu(as4.y + ad4.y + ak.y * ea));
            m.z = fmaxf(m.z, lrelu(as4.z + ad4.z + ak.z * ea));
            m.w = fmaxf(m.w, lrelu(as4.w + ad4.w + ak.w * ea));
        }
#pragma unroll
        for (int off = 16; off > 0; off >>= 1) {
            m.x = fmaxf(m.x, __shfl_xor_sync(0xffffffffu, m.x, off));
            m.y = fmaxf(m.y, __shfl_xor_sync(0xffffffffu, m.y, off));
            m.z = fmaxf(m.z, __shfl_xor_sync(0xffffffffu, m.z, off));
            m.w = fmaxf(m.w, __shfl_xor_sync(0xffffffffu, m.w, off));
        }
        if (lane == 0) { s_red[warp * 4] = m.x; s_red[warp * 4 + 1] = m.y;
                         s_red[warp * 4 + 2] = m.z; s_red[warp * 4 + 3] = m.w; }
        __syncthreads();
        if (t == 0) {
            float4 r = make_float4(s_red[0], s_red[1], s_red[2], s_red[3]);
            for (int w2 = 1; w2 < 8; w2++) {
                r.x = fmaxf(r.x, s_red[w2 * 4]); r.y = fmaxf(r.y, s_red[w2 * 4 + 1]);
                r.z = fmaxf(r.z, s_red[w2 * 4 + 2]); r.w = fmaxf(r.w, s_red[w2 * 4 + 3]);
            }
            s_bcm[0] = r.x; s_bcm[1] = r.y; s_bcm[2] = r.z; s_bcm[3] = r.w;
        }
        __syncthreads();
        float4 m4 = make_float4(s_bcm[0], s_bcm[1], s_bcm[2], s_bcm[3]);
        float4 sm = make_float4(0.f, 0.f, 0.f, 0.f);
        for (int i = t; i < deg; i += 256) {
            int e = g_eid[lo + i];
            int s = src[e];
            float4 as4 = *(const float4*)&g_as[s * 4];
            float ea = eattr[e];
            sm.x += expf(lrelu(as4.x + ad4.x + ak.x * ea) - m4.x);
            sm.y += expf(lrelu(as4.y + ad4.y + ak.y * ea) - m4.y);
            sm.z += expf(lrelu(as4.z + ad4.z + ak.z * ea) - m4.z);
            sm.w += expf(lrelu(as4.w + ad4.w + ak.w * ea) - m4.w);
        }
#pragma unroll
        for (int off = 16; off > 0; off >>= 1) {
            sm.x += __shfl_xor_sync(0xffffffffu, sm.x, off);
            sm.y += __shfl_xor_sync(0xffffffffu, sm.y, off);
            sm.z += __shfl_xor_sync(0xffffffffu, sm.z, off);
            sm.w += __shfl_xor_sync(0xffffffffu, sm.w, off);
        }
        if (lane == 0) { s_red[warp * 4] = sm.x; s_red[warp * 4 + 1] = sm.y;
                         s_red[warp * 4 + 2] = sm.z; s_red[warp * 4 + 3] = sm.w; }
        __syncthreads();
        if (t == 0) {
            float4 r = make_float4(0.f, 0.f, 0.f, 0.f);
            for (int w2 = 0; w2 < 8; w2++) {
                r.x += s_red[w2 * 4]; r.y += s_red[w2 * 4 + 1];
                r.z += s_red[w2 * 4 + 2]; r.w += s_red[w2 * 4 + 3];
            }
            s_bcd[0] = 1.f / (r.x + 1e-16f); s_bcd[1] = 1.f / (r.y + 1e-16f);
            s_bcd[2] = 1.f / (r.z + 1e-16f); s_bcd[3] = 1.f / (r.w + 1e-16f);
        }
        __syncthreads();
        float4 rd = make_float4(s_bcd[0], s_bcd[1], s_bcd[2], s_bcd[3]);
        float acc0 = 0.f;
        for (int c0 = 0; c0 < deg; c0 += MAXE) {
            int cnt = min(MAXE, deg - c0);
            for (int i = t; i < cnt; i += 256) {
                int e = g_eid[lo + c0 + i];
                int s = src[e];
                float4 as4 = *(const float4*)&g_as[s * 4];
                float ea = eattr[e];
                float4 w;
                w.x = expf(lrelu(as4.x + ad4.x + ak.x * ea) - m4.x) * rd.x;
                w.y = expf(lrelu(as4.y + ad4.y + ak.y * ea) - m4.y) * rd.y;
                w.z = expf(lrelu(as4.z + ad4.z + ak.z * ea) - m4.z) * rd.z;
                w.w = expf(lrelu(as4.w + ad4.w + ak.w * ea) - m4.w) * rd.w;
                *(float4*)&w_out[(size_t)e * 4] = w;
                float at = eatten[e];
                s_src[i] = s;
                ((float4*)s_co)[i] = make_float4(w.x * at, w.y * at, w.z * at, w.w * at);
            }
            __syncthreads();
            for (int i = 0; i < cnt; i++)
                acc0 += xh[(size_t)s_src[i] * 256 + t] * s_co[i * 4 + h];
            __syncthreads();
        }
        val = acc0 + bias[t];
    }

    // output
    if (mode == 1) {
        s_row[t] = val;
        __syncthreads();
        if (t < 128) {
            float v0 = s_row[2 * t], v1 = s_row[2 * t + 1];
            __nv_bfloat16 h0 = __float2bfloat16_rn(v0);
            __nv_bfloat16 h1b = __float2bfloat16_rn(v1);
            __nv_bfloat16 l0 = __float2bfloat16_rn(v0 - __bfloat162float(h0));
            __nv_bfloat16 l1 = __float2bfloat16_rn(v1 - __bfloat162float(h1b));
            __nv_bfloat162 ph; ph.x = h0; ph.y = h1b;
            __nv_bfloat162 pl; pl.x = l0; pl.y = l1;
            size_t base = (size_t)n * 768;
            ((__nv_bfloat162*)(g_A3 + base))[t] = ph;
            ((__nv_bfloat162*)(g_A3 + base + 256))[t] = ph;
            ((__nv_bfloat162*)(g_A3 + base + 512))[t] = pl;
        }
    } else {
        out_f32[(size_t)n * 256 + t] = val;
    }
}

// ---------------- driver ----------------------------------------------------
extern "C" void kernel_launch(void* const* d_in, const int* in_sizes, int n_in,
                              void* d_out, int out_size)
{
    const float* x      = (const float*)d_in[0];
    const int*   ei     = (const int*)d_in[1];
    const float* eattr  = (const float*)d_in[3];
    const float* eatten = (const float*)d_in[4];
    const float* W1     = (const float*)d_in[5];
    const float* as1    = (const float*)d_in[6];
    const float* ad1    = (const float*)d_in[7];
    const float* We1    = (const float*)d_in[8];
    const float* ae1    = (const float*)d_in[9];
    const float* b1     = (const float*)d_in[10];
    const float* W2     = (const float*)d_in[11];
    const float* as2    = (const float*)d_in[12];
    const float* ad2    = (const float*)d_in[13];
    const float* We2    = (const float*)d_in[14];
    const float* ae2    = (const float*)d_in[15];
    const float* b2     = (const float*)d_in[16];

    const int* src = ei;
    const int* dst = ei + EE;

    float* out    = (float*)d_out;
    float* h_out  = out;
    float* w1_out = out + (size_t)NN * FDIM;
    float* w2_out = w1_out + (size_t)EE * HH;

    float* xh = nullptr;
    __nv_bfloat16* A3 = nullptr; __nv_bfloat16* B3 = nullptr;
    cudaGetSymbolAddress((void**)&xh, g_xh);
    cudaGetSymbolAddress((void**)&A3, g_A3);
    cudaGetSymbolAddress((void**)&B3, g_B3);

    const dim3 ggrid(2, (NN + 127) / 128);
    const int EB4 = (EE + 1023) / 1024;

    // CSR by dst (shared by both layers)
    k_zero<<<(NN + 255) / 256, 256>>>();
    k_deg<<<EB4, 256>>>(dst);
    k_scan<<<1, 1024>>>();
    k_fill<<<EB4, 256>>>(dst);

    // ---- layer 1 ----
    k_cvtA<<<(NN * 128 + 255) / 256, 256>>>(x, 128, NN * 128);
    k_cvtW<<<(128 * 256 + 255) / 256, 256>>>(W1, 128);
    k_gemm_mma<<<ggrid, 256>>>(A3, B3, xh, 384);
    k_asad<<<NN, 256>>>(xh, as1, ad1, We1, ae1);
    k_edge<<<NN, 256>>>(src, eattr, eatten, xh, b1, w1_out, nullptr, 1);

    // ---- layer 2 ----
    k_cvtW<<<(256 * 256 + 255) / 256, 256>>>(W2, 256);
    k_gemm_mma<<<ggrid, 256>>>(A3, B3, xh, 768);
    k_asad<<<NN, 256>>>(xh, as2, ad2, We2, ae2);
    k_edge<<<NN, 256>>>(src, eattr, eatten, xh, b2, w2_out, h_out, 0);
}

// round 5
// speedup vs baseline: 1.1910x; 1.1910x over previous
#include <cuda_runtime.h>
#include <cuda_bf16.h>
#include <cuda_fp16.h>
#include <math.h>
#include <stdint.h>

#define NN 20000
#define NNPAD 20096          // 157 * 128
#define EE 640000
#define HH 4
#define FDIM 256
#define MAXE 512

// ---------------- scratch ----------------------------------------------------
__device__ float g_xh[NN * FDIM];     // fp32 GEMM output (for asad)
__device__ __half g_xhh[NN * FDIM];   // fp16 copy (for aggregation gather)
__device__ float g_as[NN * HH];
__device__ float g_ad[NN * HH];
__device__ float g_alpha[EE * HH];
__device__ float g_coeff[EE * HH];
__device__ float g_amax[NN * HH];
__device__ float g_den[NN * HH];
__device__ float g_aek[HH];
__device__ int   g_deg[NN];
__device__ int   g_rowptr[NN + 1];
__device__ int   g_cursor[NN];
__device__ int   g_eid[EE];
__device__ __nv_bfloat16 g_A3[(size_t)NNPAD * 768];
__device__ __nv_bfloat16 g_B3[768 * 256];

// ---------------- helpers ----------------------------------------------------
__device__ __forceinline__ uint32_t smem_u32(const void* p) {
    uint32_t a;
    asm("{ .reg .u64 t; cvta.to.shared.u64 t, %1; cvt.u32.u64 %0, t; }" : "=r"(a) : "l"(p));
    return a;
}
__device__ __forceinline__ void ldsm_x4(uint32_t addr, uint32_t& r0, uint32_t& r1,
                                        uint32_t& r2, uint32_t& r3) {
    asm volatile("ldmatrix.sync.aligned.m8n8.x4.shared.b16 {%0,%1,%2,%3}, [%4];"
                 : "=r"(r0), "=r"(r1), "=r"(r2), "=r"(r3) : "r"(addr));
}
__device__ __forceinline__ void ldsm_x4t(uint32_t addr, uint32_t& r0, uint32_t& r1,
                                         uint32_t& r2, uint32_t& r3) {
    asm volatile("ldmatrix.sync.aligned.m8n8.x4.trans.shared.b16 {%0,%1,%2,%3}, [%4];"
                 : "=r"(r0), "=r"(r1), "=r"(r2), "=r"(r3) : "r"(addr));
}
__device__ __forceinline__ void mma16816(float* d, const uint32_t* a, uint32_t b0, uint32_t b1) {
    asm volatile(
        "mma.sync.aligned.m16n8k16.row.col.f32.bf16.bf16.f32 "
        "{%0,%1,%2,%3}, {%4,%5,%6,%7}, {%8,%9}, {%0,%1,%2,%3};"
        : "+f"(d[0]), "+f"(d[1]), "+f"(d[2]), "+f"(d[3])
        : "r"(a[0]), "r"(a[1]), "r"(a[2]), "r"(a[3]), "r"(b0), "r"(b1));
}
__device__ __forceinline__ float lrelu(float x) { return x > 0.f ? x : 0.2f * x; }

// ---------------- CSR build (round-3 proven config) --------------------------
__global__ void k_zero()
{
    int i = blockIdx.x * blockDim.x + threadIdx.x;
    if (i < NN) { g_deg[i] = 0; g_cursor[i] = 0; }
}

__global__ void k_deg(const int* __restrict__ dst)
{
    int e = blockIdx.x * blockDim.x + threadIdx.x;
    if (e < EE) atomicAdd(&g_deg[dst[e]], 1);
}

__global__ void k_scan()
{
    __shared__ int s[1024];
    int t = threadIdx.x;
    const int CH = (NN + 1023) / 1024;
    int base = t * CH;
    int sum = 0;
    for (int i = 0; i < CH; i++) {
        int idx = base + i;
        if (idx < NN) sum += g_deg[idx];
    }
    s[t] = sum;
    __syncthreads();
    for (int off = 1; off < 1024; off <<= 1) {
        int v = (t >= off) ? s[t - off] : 0;
        __syncthreads();
        s[t] += v;
        __syncthreads();
    }
    int run = s[t] - sum;
    for (int i = 0; i < CH; i++) {
        int idx = base + i;
        if (idx < NN) { g_rowptr[idx] = run; run += g_deg[idx]; }
    }
    if (t == 1023) g_rowptr[NN] = s[1023];
}

__global__ void k_fill(const int* __restrict__ dst)
{
    int e = blockIdx.x * blockDim.x + threadIdx.x;
    if (e >= EE) return;
    int d = dst[e];
    int pos = atomicAdd(&g_cursor[d], 1);
    g_eid[g_rowptr[d] + pos] = e;
}

// ---------------- bf16-split conversions ------------------------------------
__global__ void k_cvtA(const float* __restrict__ src, int K, int total)
{
    int i = blockIdx.x * blockDim.x + threadIdx.x;
    if (i >= total) return;
    int m = i / K, k = i - m * K;
    float v = src[i];
    __nv_bfloat16 h = __float2bfloat16_rn(v);
    __nv_bfloat16 l = __float2bfloat16_rn(v - __bfloat162float(h));
    size_t base = (size_t)m * (3 * K);
    g_A3[base + k] = h;
    g_A3[base + K + k] = h;
    g_A3[base + 2 * K + k] = l;
}

__global__ void k_cvtW(const float* __restrict__ W, int K)
{
    int i = blockIdx.x * blockDim.x + threadIdx.x;
    if (i >= K * 256) return;
    int k = i >> 8, n = i & 255;
    float v = W[i];
    __nv_bfloat16 h = __float2bfloat16_rn(v);
    __nv_bfloat16 l = __float2bfloat16_rn(v - __bfloat162float(h));
    g_B3[(size_t)k * 256 + n] = h;
    g_B3[(size_t)(K + k) * 256 + n] = l;
    g_B3[(size_t)(2 * K + k) * 256 + n] = h;
}

// ---------------- HMMA GEMM: C[M,256] = A'[M,K'] @ B'[K',256] ---------------
#define ASTR 40
#define BSTR 136

__device__ __forceinline__ void gemm_load(uint32_t as_dst, uint32_t bs_dst,
                                          const __nv_bfloat16* __restrict__ A,
                                          const __nv_bfloat16* __restrict__ B,
                                          int row0, int n0, int k0, int Kp, int tid)
{
#pragma unroll
    for (int c = tid; c < 512; c += 256) {
        int r = c >> 2, off = c & 3;
        uint32_t d = as_dst + (uint32_t)(r * ASTR + off * 8) * 2;
        const void* s = A + (size_t)(row0 + r) * Kp + k0 + off * 8;
        asm volatile("cp.async.cg.shared.global [%0], [%1], 16;" :: "r"(d), "l"(s));
    }
#pragma unroll
    for (int c = tid; c < 512; c += 256) {
        int r = c >> 4, off = c & 15;
        uint32_t d = bs_dst + (uint32_t)(r * BSTR + off * 8) * 2;
        const void* s = B + (size_t)(k0 + r) * 256 + n0 + off * 8;
        asm volatile("cp.async.cg.shared.global [%0], [%1], 16;" :: "r"(d), "l"(s));
    }
    asm volatile("cp.async.commit_group;");
}

__global__ void __launch_bounds__(256, 2)
k_gemm_mma(const __nv_bfloat16* __restrict__ A, const __nv_bfloat16* __restrict__ B,
           float* __restrict__ C, __half* __restrict__ Ch, int Kp)
{
    __shared__ __align__(16) __nv_bfloat16 As[2][128 * ASTR];
    __shared__ __align__(16) __nv_bfloat16 Bs[2][32 * BSTR];
    int tid = threadIdx.x;
    int wid = tid >> 5, lane = tid & 31;
    int row0 = blockIdx.y * 128;
    int n0 = blockIdx.x * 128;
    int wm = (wid >> 2) * 64;
    int wn = (wid & 3) * 32;

    float acc[4][4][4];
#pragma unroll
    for (int i = 0; i < 4; i++)
#pragma unroll
        for (int j = 0; j < 4; j++)
#pragma unroll
            for (int q = 0; q < 4; q++) acc[i][j][q] = 0.f;

    uint32_t asb = smem_u32(As), bsb = smem_u32(Bs);
    const int NIT = Kp >> 5;

    gemm_load(asb, bsb, A, B, row0, n0, 0, Kp, tid);

    for (int it = 0; it < NIT; it++) {
        int buf = it & 1;
        if (it + 1 < NIT) {
            gemm_load(asb + ((it + 1) & 1) * 128 * ASTR * 2,
                      bsb + ((it + 1) & 1) * 32 * BSTR * 2,
                      A, B, row0, n0, (it + 1) * 32, Kp, tid);
            asm volatile("cp.async.wait_group 1;");
        } else {
            asm volatile("cp.async.wait_group 0;");
        }
        __syncthreads();

        uint32_t abuf = asb + buf * 128 * ASTR * 2;
        uint32_t bbuf = bsb + buf * 32 * BSTR * 2;
#pragma unroll
        for (int ks = 0; ks < 32; ks += 16) {
            uint32_t af[4][4];
            int arow = wm + (lane & 7) + ((lane & 8) ? 8 : 0);
            int acol = ks + ((lane & 16) ? 8 : 0);
#pragma unroll
            for (int ms = 0; ms < 4; ms++) {
                uint32_t ad = abuf + (uint32_t)((arow + ms * 16) * ASTR + acol) * 2;
                ldsm_x4(ad, af[ms][0], af[ms][1], af[ms][2], af[ms][3]);
            }
            uint32_t bfr[2][4];
            int bk = ks + ((lane & 8) ? 8 : 0) + (lane & 7);
            int bnl = ((lane & 16) ? 8 : 0);
#pragma unroll
            for (int p = 0; p < 2; p++) {
                uint32_t bd = bbuf + (uint32_t)(bk * BSTR + wn + p * 16 + bnl) * 2;
                ldsm_x4t(bd, bfr[p][0], bfr[p][1], bfr[p][2], bfr[p][3]);
            }
#pragma unroll
            for (int ms = 0; ms < 4; ms++)
#pragma unroll
                for (int ns = 0; ns < 4; ns++) {
                    int p = ns >> 1, q = ns & 1;
                    mma16816(acc[ms][ns], af[ms], bfr[p][q * 2], bfr[p][q * 2 + 1]);
                }
        }
        __syncthreads();
    }

#pragma unroll
    for (int ms = 0; ms < 4; ms++) {
        int r0 = row0 + wm + ms * 16 + (lane >> 2);
#pragma unroll
        for (int ns = 0; ns < 4; ns++) {
            int cc = n0 + wn + ns * 8 + (lane & 3) * 2;
            if (r0 < NN) {
                C[(size_t)r0 * 256 + cc]     = acc[ms][ns][0];
                C[(size_t)r0 * 256 + cc + 1] = acc[ms][ns][1];
                *(__half2*)&Ch[(size_t)r0 * 256 + cc] =
                    __floats2half2_rn(acc[ms][ns][0], acc[ms][ns][1]);
            }
            if (r0 + 8 < NN) {
                C[(size_t)(r0 + 8) * 256 + cc]     = acc[ms][ns][2];
                C[(size_t)(r0 + 8) * 256 + cc + 1] = acc[ms][ns][3];
                *(__half2*)&Ch[(size_t)(r0 + 8) * 256 + cc] =
                    __floats2half2_rn(acc[ms][ns][2], acc[ms][ns][3]);
            }
        }
    }
}

// ---------------- alpha_src / alpha_dst per node ----------------------------
__global__ void k_asad(const float* __restrict__ xh,
                       const float* __restrict__ a_src,
                       const float* __restrict__ a_dst)
{
    int n = blockIdx.x;
    int t = threadIdx.x;  // 256
    float v = xh[(size_t)n * FDIM + t];
    float ps = v * a_src[t];
    float pd = v * a_dst[t];
#pragma unroll
    for (int off = 16; off > 0; off >>= 1) {
        ps += __shfl_down_sync(0xffffffffu, ps, off);
        pd += __shfl_down_sync(0xffffffffu, pd, off);
    }
    __shared__ float ss[8], sd[8];
    int w = t >> 5, lane = t & 31;
    if (lane == 0) { ss[w] = ps; sd[w] = pd; }
    __syncthreads();
    if (t < HH) {
        g_as[n * HH + t] = ss[2 * t] + ss[2 * t + 1];
        g_ad[n * HH + t] = sd[2 * t] + sd[2 * t + 1];
    }
}

__global__ void k_aek(const float* __restrict__ We, const float* __restrict__ ae)
{
    int t = threadIdx.x;  // 256
    float p = We[t] * ae[t];
#pragma unroll
    for (int off = 16; off > 0; off >>= 1)
        p += __shfl_down_sync(0xffffffffu, p, off);
    __shared__ float sh[8];
    int w = t >> 5, lane = t & 31;
    if (lane == 0) sh[w] = p;
    __syncthreads();
    if (t < HH) g_aek[t] = sh[2 * t] + sh[2 * t + 1];
}

// ---------------- per-edge logits ------------------------------------------
__global__ void k_alpha(const int* __restrict__ src, const int* __restrict__ dst,
                        const float* __restrict__ eattr)
{
    int e = blockIdx.x * blockDim.x + threadIdx.x;
    if (e >= EE) return;
    int s = src[e], d = dst[e];
    float ea = eattr[e];
    float4 as = *(const float4*)&g_as[s * 4];
    float4 ad = *(const float4*)&g_ad[d * 4];
    float4 ak = *(const float4*)g_aek;
    float4 a;
    a.x = lrelu(as.x + ad.x + ak.x * ea);
    a.y = lrelu(as.y + ad.y + ak.y * ea);
    a.z = lrelu(as.z + ad.z + ak.z * ea);
    a.w = lrelu(as.w + ad.w + ak.w * ea);
    *(float4*)&g_alpha[e * 4] = a;
}

// ---------------- per-node segment max + sum(exp) ---------------------------
__global__ void k_softmax()
{
    int warp = threadIdx.x >> 5;
    int lane = threadIdx.x & 31;
    int n = blockIdx.x * 4 + warp;
    if (n >= NN) return;
    int lo = g_rowptr[n], hi = g_rowptr[n + 1];
    float4 m = make_float4(-INFINITY, -INFINITY, -INFINITY, -INFINITY);
    for (int i = lo + lane; i < hi; i += 32) {
        int e = g_eid[i];
        float4 a = *(const float4*)&g_alpha[e * 4];
        m.x = fmaxf(m.x, a.x); m.y = fmaxf(m.y, a.y);
        m.z = fmaxf(m.z, a.z); m.w = fmaxf(m.w, a.w);
    }
#pragma unroll
    for (int off = 16; off > 0; off >>= 1) {
        m.x = fmaxf(m.x, __shfl_xor_sync(0xffffffffu, m.x, off));
        m.y = fmaxf(m.y, __shfl_xor_sync(0xffffffffu, m.y, off));
        m.z = fmaxf(m.z, __shfl_xor_sync(0xffffffffu, m.z, off));
        m.w = fmaxf(m.w, __shfl_xor_sync(0xffffffffu, m.w, off));
    }
    float4 s4 = make_float4(0.f, 0.f, 0.f, 0.f);
    for (int i = lo + lane; i < hi; i += 32) {
        int e = g_eid[i];
        float4 a = *(const float4*)&g_alpha[e * 4];
        s4.x += expf(a.x - m.x); s4.y += expf(a.y - m.y);
        s4.z += expf(a.z - m.z); s4.w += expf(a.w - m.w);
    }
#pragma unroll
    for (int off = 16; off > 0; off >>= 1) {
        s4.x += __shfl_xor_sync(0xffffffffu, s4.x, off);
        s4.y += __shfl_xor_sync(0xffffffffu, s4.y, off);
        s4.z += __shfl_xor_sync(0xffffffffu, s4.z, off);
        s4.w += __shfl_xor_sync(0xffffffffu, s4.w, off);
    }
    if (lane == 0) {
        *(float4*)&g_amax[n * 4] = m;
        *(float4*)&g_den[n * 4] = s4;
    }
}

// ---------------- per-edge normalize ----------------------------------------
__global__ void k_norm(const int* __restrict__ dst, const float* __restrict__ eatten,
                       float* __restrict__ w_out)
{
    int e = blockIdx.x * blockDim.x + threadIdx.x;
    if (e >= EE) return;
    int d = dst[e];
    float4 a = *(const float4*)&g_alpha[e * 4];
    float4 m = *(const float4*)&g_amax[d * 4];
    float4 dn = *(const float4*)&g_den[d * 4];
    float at = eatten[e];
    float4 w;
    w.x = expf(a.x - m.x) / (dn.x + 1e-16f);
    w.y = expf(a.y - m.y) / (dn.y + 1e-16f);
    w.z = expf(a.z - m.z) / (dn.z + 1e-16f);
    w.w = expf(a.w - m.w) / (dn.w + 1e-16f);
    *(float4*)&w_out[e * 4] = w;
    float4 c = make_float4(w.x * at, w.y * at, w.z * at, w.w * at);
    *(float4*)&g_coeff[e * 4] = c;
}

// ---------------- aggregation: fp16 gather, 128 thr, half2 per thread -------
// mode 1: write split-bf16 triple to g_A3 (layer 1); mode 0: fp32 out (layer 2)
__global__ void __launch_bounds__(128)
k_agg16(const int* __restrict__ src, const __half* __restrict__ xhh,
        const float* __restrict__ bias, float* __restrict__ out_f32, int mode)
{
    __shared__ int   s_src[MAXE];
    __shared__ float s_co[MAXE * 4];
    int n = blockIdx.x;
    int t = threadIdx.x;         // 128; channels 2t, 2t+1
    int h = t >> 5;              // head = (2t)/64
    int lo = g_rowptr[n], hi = g_rowptr[n + 1];
    float acc0 = 0.f, acc1 = 0.f;

    for (int base = lo; base < hi; base += MAXE) {
        int cnt = min(MAXE, hi - base);
        for (int i = t; i < cnt; i += 128) {
            int e = g_eid[base + i];
            s_src[i] = src[e];
            ((float4*)s_co)[i] = *(const float4*)&g_coeff[(size_t)e * 4];
        }
        __syncthreads();
        int i = 0;
        for (; i + 3 < cnt; i += 4) {
            __half2 u0 = *(const __half2*)&xhh[(size_t)s_src[i] * 256 + 2 * t];
            __half2 u1 = *(const __half2*)&xhh[(size_t)s_src[i + 1] * 256 + 2 * t];
            __half2 u2 = *(const __half2*)&xhh[(size_t)s_src[i + 2] * 256 + 2 * t];
            __half2 u3 = *(const __half2*)&xhh[(size_t)s_src[i + 3] * 256 + 2 * t];
            float c0 = s_co[i * 4 + h], c1 = s_co[(i + 1) * 4 + h];
            float c2 = s_co[(i + 2) * 4 + h], c3 = s_co[(i + 3) * 4 + h];
            float2 f0 = __half22float2(u0), f1 = __half22float2(u1);
            float2 f2 = __half22float2(u2), f3 = __half22float2(u3);
            acc0 += f0.x * c0 + f1.x * c1 + f2.x * c2 + f3.x * c3;
            acc1 += f0.y * c0 + f1.y * c1 + f2.y * c2 + f3.y * c3;
        }
        for (; i < cnt; i++) {
            __half2 u = *(const __half2*)&xhh[(size_t)s_src[i] * 256 + 2 * t];
            float c = s_co[i * 4 + h];
            float2 f = __half22float2(u);
            acc0 += f.x * c;
            acc1 += f.y * c;
        }
        __syncthreads();
    }

    float v0 = acc0 + bias[2 * t];
    float v1 = acc1 + bias[2 * t + 1];
    if (mode) {
        __nv_bfloat16 h0 = __float2bfloat16_rn(v0);
        __nv_bfloat16 h1b = __float2bfloat16_rn(v1);
        __nv_bfloat16 l0 = __float2bfloat16_rn(v0 - __bfloat162float(h0));
        __nv_bfloat16 l1 = __float2bfloat16_rn(v1 - __bfloat162float(h1b));
        __nv_bfloat162 ph; ph.x = h0; ph.y = h1b;
        __nv_bfloat162 pl; pl.x = l0; pl.y = l1;
        size_t base = (size_t)n * 768;
        ((__nv_bfloat162*)(g_A3 + base))[t] = ph;
        ((__nv_bfloat162*)(g_A3 + base + 256))[t] = ph;
        ((__nv_bfloat162*)(g_A3 + base + 512))[t] = pl;
    } else {
        out_f32[(size_t)n * 256 + 2 * t]     = v0;
        out_f32[(size_t)n * 256 + 2 * t + 1] = v1;
    }
}

// ---------------- driver ----------------------------------------------------
extern "C" void kernel_launch(void* const* d_in, const int* in_sizes, int n_in,
                              void* d_out, int out_size)
{
    const float* x      = (const float*)d_in[0];
    const int*   ei     = (const int*)d_in[1];
    const float* eattr  = (const float*)d_in[3];
    const float* eatten = (const float*)d_in[4];
    const float* W1     = (const float*)d_in[5];
    const float* as1    = (const float*)d_in[6];
    const float* ad1    = (const float*)d_in[7];
    const float* We1    = (const float*)d_in[8];
    const float* ae1    = (const float*)d_in[9];
    const float* b1     = (const float*)d_in[10];
    const float* W2     = (const float*)d_in[11];
    const float* as2    = (const float*)d_in[12];
    const float* ad2    = (const float*)d_in[13];
    const float* We2    = (const float*)d_in[14];
    const float* ae2    = (const float*)d_in[15];
    const float* b2     = (const float*)d_in[16];

    const int* src = ei;
    const int* dst = ei + EE;

    float* out    = (float*)d_out;
    float* h_out  = out;
    float* w1_out = out + (size_t)NN * FDIM;
    float* w2_out = w1_out + (size_t)EE * HH;

    float* xh = nullptr;
    __half* xhh = nullptr;
    __nv_bfloat16* A3 = nullptr; __nv_bfloat16* B3 = nullptr;
    cudaGetSymbolAddress((void**)&xh, g_xh);
    cudaGetSymbolAddress((void**)&xhh, g_xhh);
    cudaGetSymbolAddress((void**)&A3, g_A3);
    cudaGetSymbolAddress((void**)&B3, g_B3);

    const int EB = (EE + 255) / 256;
    const dim3 ggrid(2, (NN + 127) / 128);

    // CSR by dst (shared by both layers)
    k_zero<<<(NN + 255) / 256, 256>>>();
    k_deg<<<EB, 256>>>(dst);
    k_scan<<<1, 1024>>>();
    k_fill<<<EB, 256>>>(dst);

    // ---- layer 1 ----
    k_cvtA<<<(NN * 128 + 255) / 256, 256>>>(x, 128, NN * 128);
    k_cvtW<<<(128 * 256 + 255) / 256, 256>>>(W1, 128);
    k_gemm_mma<<<ggrid, 256>>>(A3, B3, xh, xhh, 384);
    k_asad<<<NN, 256>>>(xh, as1, ad1);
    k_aek<<<1, 256>>>(We1, ae1);
    k_alpha<<<EB, 256>>>(src, dst, eattr);
    k_softmax<<<(NN + 3) / 4, 128>>>();
    k_norm<<<EB, 256>>>(dst, eatten, w1_out);
    k_agg16<<<NN, 128>>>(src, xhh, b1, nullptr, 1);

    // ---- layer 2 ----
    k_cvtW<<<(256 * 256 + 255) / 256, 256>>>(W2, 256);
    k_gemm_mma<<<ggrid, 256>>>(A3, B3, xh, xhh, 768);
    k_asad<<<NN, 256>>>(xh, as2, ad2);
    k_aek<<<1, 256>>>(We2, ae2);
    k_alpha<<<EB, 256>>>(src, dst, eattr);
    k_softmax<<<(NN + 3) / 4, 128>>>();
    k_norm<<<EB, 256>>>(dst, eatten, w2_out);
    k_agg16<<<NN, 128>>>(src, xhh, b2, h_out, 0);
}

// round 6
// speedup vs baseline: 1.3440x; 1.1284x over previous
#include <cuda_runtime.h>
#include <cuda_bf16.h>
#include <cuda_fp16.h>
#include <math.h>
#include <stdint.h>

#define NN 20000
#define NNPAD 20096          // 157 * 128
#define EE 640000
#define HH 4
#define FDIM 256
#define MAXE 512

// ---------------- scratch ----------------------------------------------------
__device__ float g_xh[NN * FDIM];     // fp32 GEMM output
__device__ __half g_xhh[NN * FDIM];   // fp16 copy (aggregation gather)
__device__ float g_as[NN * HH];
__device__ float g_ad[NN * HH];
__device__ float g_coeff[EE * HH];
__device__ float g_aek[HH];
__device__ int   g_deg[NN];
__device__ int   g_rowptr[NN + 1];
__device__ int   g_cursor[NN];
__device__ int   g_eid[EE];
__device__ __nv_bfloat16 g_A3[(size_t)NNPAD * 768];
__device__ __nv_bfloat16 g_B3[768 * 256];

// ---------------- helpers ----------------------------------------------------
__device__ __forceinline__ uint32_t smem_u32(const void* p) {
    uint32_t a;
    asm("{ .reg .u64 t; cvta.to.shared.u64 t, %1; cvt.u32.u64 %0, t; }" : "=r"(a) : "l"(p));
    return a;
}
__device__ __forceinline__ void ldsm_x4(uint32_t addr, uint32_t& r0, uint32_t& r1,
                                        uint32_t& r2, uint32_t& r3) {
    asm volatile("ldmatrix.sync.aligned.m8n8.x4.shared.b16 {%0,%1,%2,%3}, [%4];"
                 : "=r"(r0), "=r"(r1), "=r"(r2), "=r"(r3) : "r"(addr));
}
__device__ __forceinline__ void ldsm_x4t(uint32_t addr, uint32_t& r0, uint32_t& r1,
                                         uint32_t& r2, uint32_t& r3) {
    asm volatile("ldmatrix.sync.aligned.m8n8.x4.trans.shared.b16 {%0,%1,%2,%3}, [%4];"
                 : "=r"(r0), "=r"(r1), "=r"(r2), "=r"(r3) : "r"(addr));
}
__device__ __forceinline__ void mma16816(float* d, const uint32_t* a, uint32_t b0, uint32_t b1) {
    asm volatile(
        "mma.sync.aligned.m16n8k16.row.col.f32.bf16.bf16.f32 "
        "{%0,%1,%2,%3}, {%4,%5,%6,%7}, {%8,%9}, {%0,%1,%2,%3};"
        : "+f"(d[0]), "+f"(d[1]), "+f"(d[2]), "+f"(d[3])
        : "r"(a[0]), "r"(a[1]), "r"(a[2]), "r"(a[3]), "r"(b0), "r"(b1));
}
__device__ __forceinline__ float lrelu(float x) { return x > 0.f ? x : 0.2f * x; }

// ---------------- CSR build --------------------------------------------------
__global__ void k_zero()
{
    int i = blockIdx.x * blockDim.x + threadIdx.x;
    if (i < NN) {
        g_deg[i] = 0; g_cursor[i] = 0;
        *(float4*)&g_as[i * 4] = make_float4(0.f, 0.f, 0.f, 0.f);
        *(float4*)&g_ad[i * 4] = make_float4(0.f, 0.f, 0.f, 0.f);
    }
}

__global__ void k_deg(const int* __restrict__ dst)
{
    int e = blockIdx.x * blockDim.x + threadIdx.x;
    if (e < EE) atomicAdd(&g_deg[dst[e]], 1);
}

__global__ void k_scan()
{
    __shared__ int s[1024];
    int t = threadIdx.x;
    const int CH = (NN + 1023) / 1024;
    int base = t * CH;
    int sum = 0;
    for (int i = 0; i < CH; i++) {
        int idx = base + i;
        if (idx < NN) sum += g_deg[idx];
    }
    s[t] = sum;
    __syncthreads();
    for (int off = 1; off < 1024; off <<= 1) {
        int v = (t >= off) ? s[t - off] : 0;
        __syncthreads();
        s[t] += v;
        __syncthreads();
    }
    int run = s[t] - sum;
    for (int i = 0; i < CH; i++) {
        int idx = base + i;
        if (idx < NN) { g_rowptr[idx] = run; run += g_deg[idx]; }
    }
    if (t == 1023) g_rowptr[NN] = s[1023];
}

__global__ void k_fill(const int* __restrict__ dst)
{
    int e = blockIdx.x * blockDim.x + threadIdx.x;
    if (e >= EE) return;
    int d = dst[e];
    int pos = atomicAdd(&g_cursor[d], 1);
    g_eid[g_rowptr[d] + pos] = e;
}

// ---------------- bf16-split conversions ------------------------------------
__global__ void k_cvtA(const float* __restrict__ src, int K, int total)
{
    int i = blockIdx.x * blockDim.x + threadIdx.x;
    if (i >= total) return;
    int m = i / K, k = i - m * K;
    float v = src[i];
    __nv_bfloat16 h = __float2bfloat16_rn(v);
    __nv_bfloat16 l = __float2bfloat16_rn(v - __bfloat162float(h));
    size_t base = (size_t)m * (3 * K);
    g_A3[base + k] = h;
    g_A3[base + K + k] = h;
    g_A3[base + 2 * K + k] = l;
}

__global__ void k_cvtW(const float* __restrict__ W, int K)
{
    int i = blockIdx.x * blockDim.x + threadIdx.x;
    if (i >= K * 256) return;
    int k = i >> 8, n = i & 255;
    float v = W[i];
    __nv_bfloat16 h = __float2bfloat16_rn(v);
    __nv_bfloat16 l = __float2bfloat16_rn(v - __bfloat162float(h));
    g_B3[(size_t)k * 256 + n] = h;
    g_B3[(size_t)(K + k) * 256 + n] = l;
    g_B3[(size_t)(2 * K + k) * 256 + n] = h;
}

// ---------------- HMMA GEMM + fused alpha_src/dst partial dots --------------
#define ASTR 40
#define BSTR 136

__device__ __forceinline__ void gemm_load(uint32_t as_dst, uint32_t bs_dst,
                                          const __nv_bfloat16* __restrict__ A,
                                          const __nv_bfloat16* __restrict__ B,
                                          int row0, int n0, int k0, int Kp, int tid)
{
#pragma unroll
    for (int c = tid; c < 512; c += 256) {
        int r = c >> 2, off = c & 3;
        uint32_t d = as_dst + (uint32_t)(r * ASTR + off * 8) * 2;
        const void* s = A + (size_t)(row0 + r) * Kp + k0 + off * 8;
        asm volatile("cp.async.cg.shared.global [%0], [%1], 16;" :: "r"(d), "l"(s));
    }
#pragma unroll
    for (int c = tid; c < 512; c += 256) {
        int r = c >> 4, off = c & 15;
        uint32_t d = bs_dst + (uint32_t)(r * BSTR + off * 8) * 2;
        const void* s = B + (size_t)(k0 + r) * 256 + n0 + off * 8;
        asm volatile("cp.async.cg.shared.global [%0], [%1], 16;" :: "r"(d), "l"(s));
    }
    asm volatile("cp.async.commit_group;");
}

__global__ void __launch_bounds__(256, 2)
k_gemm_mma(const __nv_bfloat16* __restrict__ A, const __nv_bfloat16* __restrict__ B,
           float* __restrict__ C, __half* __restrict__ Ch, int Kp,
           const float* __restrict__ a_src, const float* __restrict__ a_dst)
{
    __shared__ __align__(16) __nv_bfloat16 As[2][128 * ASTR];
    __shared__ __align__(16) __nv_bfloat16 Bs[2][32 * BSTR];
    int tid = threadIdx.x;
    int wid = tid >> 5, lane = tid & 31;
    int row0 = blockIdx.y * 128;
    int n0 = blockIdx.x * 128;
    int wm = (wid >> 2) * 64;
    int wn = (wid & 3) * 32;

    float acc[4][4][4];
#pragma unroll
    for (int i = 0; i < 4; i++)
#pragma unroll
        for (int j = 0; j < 4; j++)
#pragma unroll
            for (int q = 0; q < 4; q++) acc[i][j][q] = 0.f;

    uint32_t asb = smem_u32(As), bsb = smem_u32(Bs);
    const int NIT = Kp >> 5;

    gemm_load(asb, bsb, A, B, row0, n0, 0, Kp, tid);

    for (int it = 0; it < NIT; it++) {
        int buf = it & 1;
        if (it + 1 < NIT) {
            gemm_load(asb + ((it + 1) & 1) * 128 * ASTR * 2,
                      bsb + ((it + 1) & 1) * 32 * BSTR * 2,
                      A, B, row0, n0, (it + 1) * 32, Kp, tid);
            asm volatile("cp.async.wait_group 1;");
        } else {
            asm volatile("cp.async.wait_group 0;");
        }
        __syncthreads();

        uint32_t abuf = asb + buf * 128 * ASTR * 2;
        uint32_t bbuf = bsb + buf * 32 * BSTR * 2;
#pragma unroll
        for (int ks = 0; ks < 32; ks += 16) {
            uint32_t af[4][4];
            int arow = wm + (lane & 7) + ((lane & 8) ? 8 : 0);
            int acol = ks + ((lane & 16) ? 8 : 0);
#pragma unroll
            for (int ms = 0; ms < 4; ms++) {
                uint32_t ad = abuf + (uint32_t)((arow + ms * 16) * ASTR + acol) * 2;
                ldsm_x4(ad, af[ms][0], af[ms][1], af[ms][2], af[ms][3]);
            }
            uint32_t bfr[2][4];
            int bk = ks + ((lane & 8) ? 8 : 0) + (lane & 7);
            int bnl = ((lane & 16) ? 8 : 0);
#pragma unroll
            for (int p = 0; p < 2; p++) {
                uint32_t bd = bbuf + (uint32_t)(bk * BSTR + wn + p * 16 + bnl) * 2;
                ldsm_x4t(bd, bfr[p][0], bfr[p][1], bfr[p][2], bfr[p][3]);
            }
#pragma unroll
            for (int ms = 0; ms < 4; ms++)
#pragma unroll
                for (int ns = 0; ns < 4; ns++) {
                    int p = ns >> 1, q = ns & 1;
                    mma16816(acc[ms][ns], af[ms], bfr[p][q * 2], bfr[p][q * 2 + 1]);
                }
        }
        __syncthreads();
    }

    int h = (n0 + wn) >> 6;   // this warp's 32 cols lie in a single head
#pragma unroll
    for (int ms = 0; ms < 4; ms++) {
        int r0 = row0 + wm + ms * 16 + (lane >> 2);
        float ps0 = 0.f, pd0 = 0.f, ps8 = 0.f, pd8 = 0.f;
#pragma unroll
        for (int ns = 0; ns < 4; ns++) {
            int cc = n0 + wn + ns * 8 + (lane & 3) * 2;
            float s0 = a_src[cc], s1 = a_src[cc + 1];
            float d0 = a_dst[cc], d1 = a_dst[cc + 1];
            ps0 += acc[ms][ns][0] * s0 + acc[ms][ns][1] * s1;
            pd0 += acc[ms][ns][0] * d0 + acc[ms][ns][1] * d1;
            ps8 += acc[ms][ns][2] * s0 + acc[ms][ns][3] * s1;
            pd8 += acc[ms][ns][2] * d0 + acc[ms][ns][3] * d1;
            if (r0 < NN) {
                C[(size_t)r0 * 256 + cc]     = acc[ms][ns][0];
                C[(size_t)r0 * 256 + cc + 1] = acc[ms][ns][1];
                *(__half2*)&Ch[(size_t)r0 * 256 + cc] =
                    __floats2half2_rn(acc[ms][ns][0], acc[ms][ns][1]);
            }
            if (r0 + 8 < NN) {
                C[(size_t)(r0 + 8) * 256 + cc]     = acc[ms][ns][2];
                C[(size_t)(r0 + 8) * 256 + cc + 1] = acc[ms][ns][3];
                *(__half2*)&Ch[(size_t)(r0 + 8) * 256 + cc] =
                    __floats2half2_rn(acc[ms][ns][2], acc[ms][ns][3]);
            }
        }
        // quad reduce (lanes 4k..4k+3 share rows)
        ps0 += __shfl_down_sync(0xffffffffu, ps0, 2, 4);
        ps0 += __shfl_down_sync(0xffffffffu, ps0, 1, 4);
        pd0 += __shfl_down_sync(0xffffffffu, pd0, 2, 4);
        pd0 += __shfl_down_sync(0xffffffffu, pd0, 1, 4);
        ps8 += __shfl_down_sync(0xffffffffu, ps8, 2, 4);
        ps8 += __shfl_down_sync(0xffffffffu, ps8, 1, 4);
        pd8 += __shfl_down_sync(0xffffffffu, pd8, 2, 4);
        pd8 += __shfl_down_sync(0xffffffffu, pd8, 1, 4);
        if ((lane & 3) == 0) {
            if (r0 < NN) {
                atomicAdd(&g_as[r0 * 4 + h], ps0);
                atomicAdd(&g_ad[r0 * 4 + h], pd0);
            }
            if (r0 + 8 < NN) {
                atomicAdd(&g_as[(r0 + 8) * 4 + h], ps8);
                atomicAdd(&g_ad[(r0 + 8) * 4 + h], pd8);
            }
        }
    }
}

// ---------------- K_h --------------------------------------------------------
__global__ void k_aek(const float* __restrict__ We, const float* __restrict__ ae)
{
    int t = threadIdx.x;  // 256
    float p = We[t] * ae[t];
#pragma unroll
    for (int off = 16; off > 0; off >>= 1)
        p += __shfl_down_sync(0xffffffffu, p, off);
    __shared__ float sh[8];
    int w = t >> 5, lane = t & 31;
    if (lane == 0) sh[w] = p;
    __syncthreads();
    if (t < HH) g_aek[t] = sh[2 * t] + sh[2 * t + 1];
}

// ---------------- fused alpha + softmax + norm (warp per node) ---------------
__global__ void __launch_bounds__(128)
k_fsm(const int* __restrict__ src, const float* __restrict__ eattr,
      const float* __restrict__ eatten, float* __restrict__ w_out)
{
    int warp = threadIdx.x >> 5, lane = threadIdx.x & 31;
    int n = blockIdx.x * 4 + warp;
    if (n >= NN) return;
    int lo = g_rowptr[n], hi = g_rowptr[n + 1];
    float4 ad4 = *(const float4*)&g_ad[n * 4];
    float4 ak = *(const float4*)g_aek;

    float4 aR[4]; float atR[4]; int eR[4];
    float4 m = make_float4(-INFINITY, -INFINITY, -INFINITY, -INFINITY);
#pragma unroll
    for (int j = 0; j < 4; j++) {
        int i = lo + lane + 32 * j;
        eR[j] = -1;
        if (i < hi) {
            int e = g_eid[i];
            int s = src[e];
            float4 as4 = *(const float4*)&g_as[s * 4];
            float ea = eattr[e];
            float4 a;
            a.x = lrelu(as4.x + ad4.x + ak.x * ea);
            a.y = lrelu(as4.y + ad4.y + ak.y * ea);
            a.z = lrelu(as4.z + ad4.z + ak.z * ea);
            a.w = lrelu(as4.w + ad4.w + ak.w * ea);
            aR[j] = a; eR[j] = e; atR[j] = eatten[e];
            m.x = fmaxf(m.x, a.x); m.y = fmaxf(m.y, a.y);
            m.z = fmaxf(m.z, a.z); m.w = fmaxf(m.w, a.w);
        }
    }
    for (int i = lo + lane + 128; i < hi; i += 32) {   // rare overflow
        int e = g_eid[i];
        int s = src[e];
        float4 as4 = *(const float4*)&g_as[s * 4];
        float ea = eattr[e];
        m.x = fmaxf(m.x, lrelu(as4.x + ad4.x + ak.x * ea));
        m.y = fmaxf(m.y, lrelu(as4.y + ad4.y + ak.y * ea));
        m.z = fmaxf(m.z, lrelu(as4.z + ad4.z + ak.z * ea));
        m.w = fmaxf(m.w, lrelu(as4.w + ad4.w + ak.w * ea));
    }
#pragma unroll
    for (int off = 16; off > 0; off >>= 1) {
        m.x = fmaxf(m.x, __shfl_xor_sync(0xffffffffu, m.x, off));
        m.y = fmaxf(m.y, __shfl_xor_sync(0xffffffffu, m.y, off));
        m.z = fmaxf(m.z, __shfl_xor_sync(0xffffffffu, m.z, off));
        m.w = fmaxf(m.w, __shfl_xor_sync(0xffffffffu, m.w, off));
    }

    float4 sm = make_float4(0.f, 0.f, 0.f, 0.f);
#pragma unroll
    for (int j = 0; j < 4; j++) {
        if (eR[j] >= 0) {
            sm.x += expf(aR[j].x - m.x); sm.y += expf(aR[j].y - m.y);
            sm.z += expf(aR[j].z - m.z); sm.w += expf(aR[j].w - m.w);
        }
    }
    for (int i = lo + lane + 128; i < hi; i += 32) {
        int e = g_eid[i];
        int s = src[e];
        float4 as4 = *(const float4*)&g_as[s * 4];
        float ea = eattr[e];
        sm.x += expf(lrelu(as4.x + ad4.x + ak.x * ea) - m.x);
        sm.y += expf(lrelu(as4.y + ad4.y + ak.y * ea) - m.y);
        sm.z += expf(lrelu(as4.z + ad4.z + ak.z * ea) - m.z);
        sm.w += expf(lrelu(as4.w + ad4.w + ak.w * ea) - m.w);
    }
#pragma unroll
    for (int off = 16; off > 0; off >>= 1) {
        sm.x += __shfl_xor_sync(0xffffffffu, sm.x, off);
        sm.y += __shfl_xor_sync(0xffffffffu, sm.y, off);
        sm.z += __shfl_xor_sync(0xffffffffu, sm.z, off);
        sm.w += __shfl_xor_sync(0xffffffffu, sm.w, off);
    }
    float4 rd;
    rd.x = 1.f / (sm.x + 1e-16f); rd.y = 1.f / (sm.y + 1e-16f);
    rd.z = 1.f / (sm.z + 1e-16f); rd.w = 1.f / (sm.w + 1e-16f);

#pragma unroll
    for (int j = 0; j < 4; j++) {
        if (eR[j] >= 0) {
            float4 w;
            w.x = expf(aR[j].x - m.x) * rd.x; w.y = expf(aR[j].y - m.y) * rd.y;
            w.z = expf(aR[j].z - m.z) * rd.z; w.w = expf(aR[j].w - m.w) * rd.w;
            *(float4*)&w_out[(size_t)eR[j] * 4] = w;
            float at = atR[j];
            float4 c = make_float4(w.x * at, w.y * at, w.z * at, w.w * at);
            *(float4*)&g_coeff[(size_t)eR[j] * 4] = c;
        }
    }
    for (int i = lo + lane + 128; i < hi; i += 32) {
        int e = g_eid[i];
        int s = src[e];
        float4 as4 = *(const float4*)&g_as[s * 4];
        float ea = eattr[e];
        float4 w;
        w.x = expf(lrelu(as4.x + ad4.x + ak.x * ea) - m.x) * rd.x;
        w.y = expf(lrelu(as4.y + ad4.y + ak.y * ea) - m.y) * rd.y;
        w.z = expf(lrelu(as4.z + ad4.z + ak.z * ea) - m.z) * rd.z;
        w.w = expf(lrelu(as4.w + ad4.w + ak.w * ea) - m.w) * rd.w;
        *(float4*)&w_out[(size_t)e * 4] = w;
        float at = eatten[e];
        *(float4*)&g_coeff[(size_t)e * 4] = make_float4(w.x * at, w.y * at, w.z * at, w.w * at);
    }
}

// ---------------- aggregation: fp16 gather ----------------------------------
__global__ void __launch_bounds__(128)
k_agg16(const int* __restrict__ src, const __half* __restrict__ xhh,
        const float* __restrict__ bias, float* __restrict__ out_f32, int mode)
{
    __shared__ int   s_src[MAXE];
    __shared__ float s_co[MAXE * 4];
    int n = blockIdx.x;
    int t = threadIdx.x;         // 128; channels 2t, 2t+1
    int h = t >> 5;
    int lo = g_rowptr[n], hi = g_rowptr[n + 1];
    float acc0 = 0.f, acc1 = 0.f;

    for (int base = lo; base < hi; base += MAXE) {
        int cnt = min(MAXE, hi - base);
        for (int i = t; i < cnt; i += 128) {
            int e = g_eid[base + i];
            s_src[i] = src[e];
            ((float4*)s_co)[i] = *(const float4*)&g_coeff[(size_t)e * 4];
        }
        __syncthreads();
        int i = 0;
        for (; i + 3 < cnt; i += 4) {
            __half2 u0 = *(const __half2*)&xhh[(size_t)s_src[i] * 256 + 2 * t];
            __half2 u1 = *(const __half2*)&xhh[(size_t)s_src[i + 1] * 256 + 2 * t];
            __half2 u2 = *(const __half2*)&xhh[(size_t)s_src[i + 2] * 256 + 2 * t];
            __half2 u3 = *(const __half2*)&xhh[(size_t)s_src[i + 3] * 256 + 2 * t];
            float c0 = s_co[i * 4 + h], c1 = s_co[(i + 1) * 4 + h];
            float c2 = s_co[(i + 2) * 4 + h], c3 = s_co[(i + 3) * 4 + h];
            float2 f0 = __half22float2(u0), f1 = __half22float2(u1);
            float2 f2 = __half22float2(u2), f3 = __half22float2(u3);
            acc0 += f0.x * c0 + f1.x * c1 + f2.x * c2 + f3.x * c3;
            acc1 += f0.y * c0 + f1.y * c1 + f2.y * c2 + f3.y * c3;
        }
        for (; i < cnt; i++) {
            __half2 u = *(const __half2*)&xhh[(size_t)s_src[i] * 256 + 2 * t];
            float c = s_co[i * 4 + h];
            float2 f = __half22float2(u);
            acc0 += f.x * c;
            acc1 += f.y * c;
        }
        __syncthreads();
    }

    float v0 = acc0 + bias[2 * t];
    float v1 = acc1 + bias[2 * t + 1];
    if (mode) {
        __nv_bfloat16 h0 = __float2bfloat16_rn(v0);
        __nv_bfloat16 h1b = __float2bfloat16_rn(v1);
        __nv_bfloat16 l0 = __float2bfloat16_rn(v0 - __bfloat162float(h0));
        __nv_bfloat16 l1 = __float2bfloat16_rn(v1 - __bfloat162float(h1b));
        __nv_bfloat162 ph; ph.x = h0; ph.y = h1b;
        __nv_bfloat162 pl; pl.x = l0; pl.y = l1;
        size_t base = (size_t)n * 768;
        ((__nv_bfloat162*)(g_A3 + base))[t] = ph;
        ((__nv_bfloat162*)(g_A3 + base + 256))[t] = ph;
        ((__nv_bfloat162*)(g_A3 + base + 512))[t] = pl;
    } else {
        out_f32[(size_t)n * 256 + 2 * t]     = v0;
        out_f32[(size_t)n * 256 + 2 * t + 1] = v1;
    }
}

// ---------------- driver ----------------------------------------------------
extern "C" void kernel_launch(void* const* d_in, const int* in_sizes, int n_in,
                              void* d_out, int out_size)
{
    const float* x      = (const float*)d_in[0];
    const int*   ei     = (const int*)d_in[1];
    const float* eattr  = (const float*)d_in[3];
    const float* eatten = (const float*)d_in[4];
    const float* W1     = (const float*)d_in[5];
    const float* as1    = (const float*)d_in[6];
    const float* ad1    = (const float*)d_in[7];
    const float* We1    = (const float*)d_in[8];
    const float* ae1    = (const float*)d_in[9];
    const float* b1     = (const float*)d_in[10];
    const float* W2     = (const float*)d_in[11];
    const float* as2    = (const float*)d_in[12];
    const float* ad2    = (const float*)d_in[13];
    const float* We2    = (const float*)d_in[14];
    const float* ae2    = (const float*)d_in[15];
    const float* b2     = (const float*)d_in[16];

    const int* src = ei;
    const int* dst = ei + EE;

    float* out    = (float*)d_out;
    float* h_out  = out;
    float* w1_out = out + (size_t)NN * FDIM;
    float* w2_out = w1_out + (size_t)EE * HH;

    float* xh = nullptr;
    __half* xhh = nullptr;
    __nv_bfloat16* A3 = nullptr; __nv_bfloat16* B3 = nullptr;
    float* asA = nullptr; float* adA = nullptr;
    cudaGetSymbolAddress((void**)&xh, g_xh);
    cudaGetSymbolAddress((void**)&xhh, g_xhh);
    cudaGetSymbolAddress((void**)&A3, g_A3);
    cudaGetSymbolAddress((void**)&B3, g_B3);
    cudaGetSymbolAddress((void**)&asA, g_as);
    cudaGetSymbolAddress((void**)&adA, g_ad);

    const int EB = (EE + 255) / 256;
    const dim3 ggrid(2, (NN + 127) / 128);

    // CSR by dst (shared by both layers); also zeros g_as/g_ad
    k_zero<<<(NN + 255) / 256, 256>>>();
    k_deg<<<EB, 256>>>(dst);
    k_scan<<<1, 1024>>>();
    k_fill<<<EB, 256>>>(dst);

    // ---- layer 1 ----
    k_cvtA<<<(NN * 128 + 255) / 256, 256>>>(x, 128, NN * 128);
    k_cvtW<<<(128 * 256 + 255) / 256, 256>>>(W1, 128);
    k_gemm_mma<<<ggrid, 256>>>(A3, B3, xh, xhh, 384, as1, ad1);
    k_aek<<<1, 256>>>(We1, ae1);
    k_fsm<<<(NN + 3) / 4, 128>>>(src, eattr, eatten, w1_out);
    k_agg16<<<NN, 128>>>(src, xhh, b1, nullptr, 1);

    // ---- layer 2 ----
    cudaMemsetAsync(asA, 0, NN * HH * sizeof(float));
    cudaMemsetAsync(adA, 0, NN * HH * sizeof(float));
    k_cvtW<<<(256 * 256 + 255) / 256, 256>>>(W2, 256);
    k_gemm_mma<<<ggrid, 256>>>(A3, B3, xh, xhh, 768, as2, ad2);
    k_aek<<<1, 256>>>(We2, ae2);
    k_fsm<<<(NN + 3) / 4, 128>>>(src, eattr, eatten, w2_out);
    k_agg16<<<NN, 128>>>(src, xhh, b2, h_out, 0);
}